// round 14
// baseline (speedup 1.0000x reference)
#include <cuda_runtime.h>
#include <cstdint>

#define Bz 2
#define Lz 2048
#define Dz 768
#define Hz 12
#define Ez 32
#define Tz 8
#define Wz 4
#define Rz 57
#define Nz 20
#define Pz 248            // T*(E-1)
#define ROUT (Rz + 1)     // 58
#define RN 77             // R + N rows
#define RP 80             // padded rows: 0..56 rel, 57..59 pad(zero), 60..79 nota

// -------- device scratch --------
__device__ float g_ent_emb[Bz * Ez * Dz];
__device__ float g_ent_att[(size_t)Bz * Ez * Hz * Lz];   // 6.3 MB
__device__ float g_a[(size_t)Bz * Pz * Lz];              // 4 MB (unnormalized q)
__device__ float g_zp[Bz * Pz * 4];                      // per-chunk partial sums
__device__ float g_es[Bz * Ez * RP];                     // pad rows stay 0
__device__ float g_eo[Bz * Ez * RP];
__device__ float g_srt[(size_t)Bz * RP * Lz];            // pad rows = 0 (zero weights)

__device__ __forceinline__ uint32_t f2tf(float f) {
    uint32_t u;
    asm("cvt.rna.tf32.f32 %0, %1;" : "=r"(u) : "f"(f));
    return u;
}

// ================= Kernel A: entity embeddings + entity attention =================
// grid = B*E*H = 768, 256 threads
__global__ void ent_kernel(const float* __restrict__ seq,
                           const float* __restrict__ att,
                           const int* __restrict__ span_starts) {
    int x = blockIdx.x;
    int h = x % Hz;
    int e = (x / Hz) % Ez;
    int b = x / (Ez * Hz);
    int start = span_starts[b * Ez + e];

    const float4* ab = (const float4*)(att + (((size_t)(b * Hz + h)) * Lz + start) * Lz);
    float4* dst = (float4*)(g_ent_att + ((size_t)((b * Ez + e) * Hz + h)) * Lz);
    for (int i = threadIdx.x; i < Lz / 4; i += 256) {
        float4 v0 = ab[i], v1 = ab[512 + i], v2 = ab[1024 + i], v3 = ab[1536 + i];
        float4 r;
        r.x = (v0.x + v1.x + v2.x + v3.x) * 0.25f;
        r.y = (v0.y + v1.y + v2.y + v3.y) * 0.25f;
        r.z = (v0.z + v1.z + v2.z + v3.z) * 0.25f;
        r.w = (v0.w + v1.w + v2.w + v3.w) * 0.25f;
        dst[i] = r;
    }

    if (h == 0) {
        const float4* sb = (const float4*)(seq + ((size_t)b * Lz + start) * Dz);
        float4* ed = (float4*)(g_ent_emb + (b * Ez + e) * Dz);
        for (int i = threadIdx.x; i < Dz / 4; i += 256) {
            float4 v0 = sb[i], v1 = sb[192 + i], v2 = sb[384 + i], v3 = sb[576 + i];
            float4 r;
            r.x = (v0.x + v1.x + v2.x + v3.x) * 0.25f;
            r.y = (v0.y + v1.y + v2.y + v3.y) * 0.25f;
            r.z = (v0.z + v1.z + v2.z + v3.z) * 0.25f;
            r.w = (v0.w + v1.w + v2.w + v3.w) * 0.25f;
            ed[i] = r;
        }
    }
}

// ================= Kernel B: unnormalized q + partial sums (s-split 2, L-split 4) =
// grid = B * 16(o-grp) * 4(s-grp of 2) * 4(chunk) = 512 blocks, 128 threads
__global__ void pair_q_kernel() {
    int x = blockIdx.x;
    int b = x >> 8;
    int rem = x & 255;
    int c = rem & 3;              // L chunk
    int sg = (rem >> 2) & 3;      // subject group (2 subjects)
    int og = rem >> 4;            // object group (2 objects)
    int o0 = og * 2;
    int s0 = sg * 2;
    int tid = threadIdx.x;
    int f4idx = c * 128 + tid;    // f4 index within row (0..511)

    const float4* aob[2];
    const float4* asb[2];
#pragma unroll
    for (int oo = 0; oo < 2; oo++)
        aob[oo] = (const float4*)(g_ent_att + ((size_t)((b * Ez + o0 + oo) * Hz)) * Lz);
#pragma unroll
    for (int js = 0; js < 2; js++)
        asb[js] = (const float4*)(g_ent_att + ((size_t)((b * Ez + s0 + js) * Hz)) * Lz);

    float4 q[2][2];
#pragma unroll
    for (int oo = 0; oo < 2; oo++)
#pragma unroll
        for (int js = 0; js < 2; js++)
            q[oo][js] = make_float4(0.f, 0.f, 0.f, 0.f);

#pragma unroll
    for (int h = 0; h < Hz; h++) {
        float4 ao0 = aob[0][h * 512 + f4idx];
        float4 ao1 = aob[1][h * 512 + f4idx];
#pragma unroll
        for (int js = 0; js < 2; js++) {
            float4 as = asb[js][h * 512 + f4idx];
            q[0][js].x += as.x * ao0.x; q[0][js].y += as.y * ao0.y;
            q[0][js].z += as.z * ao0.z; q[0][js].w += as.w * ao0.w;
            q[1][js].x += as.x * ao1.x; q[1][js].y += as.y * ao1.y;
            q[1][js].z += as.z * ao1.z; q[1][js].w += as.w * ao1.w;
        }
    }

    __shared__ float red[128][4];
#pragma unroll
    for (int oo = 0; oo < 2; oo++)
#pragma unroll
        for (int js = 0; js < 2; js++) {
            float4 t = q[oo][js];
            red[tid][oo * 2 + js] = t.x + t.y + t.z + t.w;
        }
    __syncthreads();
#pragma unroll
    for (int st = 64; st > 0; st >>= 1) {
        if (tid < st) {
#pragma unroll
            for (int k = 0; k < 4; k++) red[tid][k] += red[tid + st][k];
        }
        __syncthreads();
    }

#pragma unroll
    for (int oo = 0; oo < 2; oo++) {
        int o = o0 + oo;
#pragma unroll
        for (int js = 0; js < 2; js++) {
            int s = s0 + js;
            if (s == o) continue;
            int jj = o - (o > s ? 1 : 0);
            int p = s * (Ez - 1) + jj;
            ((float4*)(g_a + ((size_t)(b * Pz + p)) * Lz))[f4idx] = q[oo][js];
            if (tid == 0)
                g_zp[(b * Pz + p) * 4 + c] = red[0][oo * 2 + js];
        }
    }
}

// ================= Kernel C: ES/EO — one block per (b, row, entity-half) ==========
// grid = B * RN * 2 = 308, 256 threads. Writes into padded row space.
__global__ void eso_kernel(const float* __restrict__ rel,
                           const float* __restrict__ nota) {
    int x = blockIdx.x;
    int b = x / (RN * 2);
    int rr = x % (RN * 2);
    int ri = rr >> 1;
    int half = rr & 1;
    int rlog = (ri < Rz) ? ri : ri + 3;
    int tid = threadIdx.x;

    __shared__ float4 w[2 * Dz / 4];
    const float4* row = (const float4*)((ri < Rz) ? (rel + (size_t)ri * 3 * Dz)
                                                  : (nota + (size_t)(ri - Rz) * 3 * Dz));
    for (int i = tid; i < 2 * Dz / 4; i += 256) w[i] = row[i];
    __syncthreads();

    int wp = tid >> 5, ln = tid & 31;
#pragma unroll
    for (int ee = 0; ee < 2; ee++) {
        int e = half * 16 + wp + ee * 8;
        const float4* emb = (const float4*)(g_ent_emb + (b * Ez + e) * Dz);
        float es = 0.f, eo = 0.f;
#pragma unroll
        for (int i = 0; i < 6; i++) {
            int d = ln + i * 32;
            float4 e4 = emb[d];
            float4 r1 = w[d];
            float4 r2 = w[Dz / 4 + d];
            es += e4.x * r1.x + e4.y * r1.y + e4.z * r1.z + e4.w * r1.w;
            eo += e4.x * r2.x + e4.y * r2.y + e4.z * r2.z + e4.w * r2.w;
        }
#pragma unroll
        for (int off = 16; off > 0; off >>= 1) {
            es += __shfl_down_sync(0xffffffffu, es, off);
            eo += __shfl_down_sync(0xffffffffu, eo, off);
        }
        if (ln == 0) {
            g_es[(b * Ez + e) * RP + rlog] = es;
            g_eo[(b * Ez + e) * RP + rlog] = eo;
        }
    }
}

// ================= Kernel D (tf32 MMA): SR^T[b,r,l] = W3[r,:] . seq[b,l,:] =======
#define AS_STRIDE 772
#define BS_STRIDE 36
#define SRT_SMEM ((16 * AS_STRIDE + 128 * BS_STRIDE) * 4)   // 67840 B
__global__ void srt_kernel(const float* __restrict__ seq,
                           const float* __restrict__ rel,
                           const float* __restrict__ nota) {
    extern __shared__ float sm[];
    float* As = sm;
    float* Bs = sm + 16 * AS_STRIDE;

    int u = blockIdx.x;
    int b = u / 80;
    int rem = u % 80;
    int mt = rem / 16;
    int nt = rem % 16;
    int r0 = mt * 16;
    int l0 = nt * 128;
    int tid = threadIdx.x;
    int w = tid >> 5, lane = tid & 31;

#pragma unroll
    for (int i = 0; i < 12; i++) {
        int f4i = tid + i * 256;
        int rowl = f4i / 192;
        int c4 = f4i % 192;
        int r = r0 + rowl;
        float4 v = make_float4(0.f, 0.f, 0.f, 0.f);
        if (r < Rz)
            v = *(const float4*)(rel + (size_t)r * 3 * Dz + 2 * Dz + c4 * 4);
        else if (r >= 60)
            v = *(const float4*)(nota + (size_t)(r - 60) * 3 * Dz + 2 * Dz + c4 * 4);
        *(float4*)(As + rowl * AS_STRIDE + c4 * 4) = v;
    }

    float acc[2][4];
#pragma unroll
    for (int t = 0; t < 2; t++)
#pragma unroll
        for (int i = 0; i < 4; i++) acc[t][i] = 0.f;

    const float* sbase = seq + (size_t)b * Lz * Dz;
    int arow = lane >> 2, kc = lane & 3;

    for (int d0 = 0; d0 < Dz; d0 += 32) {
        __syncthreads();
#pragma unroll
        for (int i = 0; i < 4; i++) {
            int f4i = tid + i * 256;
            int ll = f4i >> 3;
            int kq = f4i & 7;
            float4 v = *(const float4*)(sbase + (size_t)(l0 + ll) * Dz + d0 + kq * 4);
            *(float4*)(Bs + ll * BS_STRIDE + kq * 4) = v;
        }
        __syncthreads();

#pragma unroll
        for (int k8 = 0; k8 < 4; k8++) {
            int dc = d0 + k8 * 8;
            uint32_t A0 = f2tf(As[arow * AS_STRIDE + dc + kc]);
            uint32_t A1 = f2tf(As[(arow + 8) * AS_STRIDE + dc + kc]);
            uint32_t A2 = f2tf(As[arow * AS_STRIDE + dc + kc + 4]);
            uint32_t A3 = f2tf(As[(arow + 8) * AS_STRIDE + dc + kc + 4]);
#pragma unroll
            for (int t = 0; t < 2; t++) {
                int nl = w * 16 + t * 8 + (lane >> 2);
                uint32_t B0 = f2tf(Bs[nl * BS_STRIDE + k8 * 8 + kc]);
                uint32_t B1 = f2tf(Bs[nl * BS_STRIDE + k8 * 8 + kc + 4]);
                asm volatile(
                    "mma.sync.aligned.m16n8k8.row.col.f32.tf32.tf32.f32 "
                    "{%0,%1,%2,%3}, {%4,%5,%6,%7}, {%8,%9}, {%0,%1,%2,%3};"
                    : "+f"(acc[t][0]), "+f"(acc[t][1]), "+f"(acc[t][2]), "+f"(acc[t][3])
                    : "r"(A0), "r"(A1), "r"(A2), "r"(A3), "r"(B0), "r"(B1));
            }
        }
    }

    int c2 = (lane & 3) * 2;
#pragma unroll
    for (int t = 0; t < 2; t++) {
        int col = l0 + w * 16 + t * 8 + c2;
        float* o0 = g_srt + ((size_t)(b * RP + r0 + arow)) * Lz + col;
        float* o1 = g_srt + ((size_t)(b * RP + r0 + arow + 8)) * Lz + col;
        *(float2*)o0 = make_float2(acc[t][0], acc[t][1]);
        *(float2*)o1 = make_float2(acc[t][2], acc[t][3]);
    }
}

// ================= Kernel E: scores = (q/Z) . SR^T + ES + EO, NOTA max ===========
// NP=4 pairs, row-split 4 (20 rows, 4 warps x 5 rows). grid = B*62*4 = 496, 128 thr.
#define NP 4
#define RQ 20
#define CH 5
__global__ void ascore_kernel(float* __restrict__ out) {
    extern __shared__ float smem[];
    float* sa = smem;                         // NP * Lz
    float* sc = smem + NP * Lz;               // RQ * NP
    float* sInv = sc + RQ * NP;               // NP

    int x = blockIdx.x;
    int b = x / (4 * (Pz / NP));
    int rem = x % (4 * (Pz / NP));
    int pt = (rem >> 2) * NP;
    int quarter = rem & 3;
    int r0 = quarter * RQ;
    int tid = threadIdx.x;

    int sarr[NP], oarr[NP];
#pragma unroll
    for (int j = 0; j < NP; j++) {
        int p = pt + j;
        int s = p / (Ez - 1);
        int jj = p % (Ez - 1);
        sarr[j] = s;
        oarr[j] = jj + (jj >= s ? 1 : 0);
    }

    if (tid < NP) {
        int p = b * Pz + pt + tid;
        sInv[tid] = 1.0f / (g_zp[p * 4] + g_zp[p * 4 + 1] +
                            g_zp[p * 4 + 2] + g_zp[p * 4 + 3]);
    }
    __syncthreads();

    float4* sa4 = (float4*)sa;
    for (int idx = tid; idx < NP * (Lz / 4); idx += 128) {
        int j = idx >> 9;
        int c = idx & 511;
        float inv = sInv[j];
        float4 v = ((const float4*)(g_a + ((size_t)(b * Pz + pt + j)) * Lz))[c];
        sa4[j * 512 + c] = make_float4(v.x * inv, v.y * inv, v.z * inv, v.w * inv);
    }
    __syncthreads();

    int w = tid >> 5, ln = tid & 31;
    int rbase = r0 + w * CH;

    float acc[CH][NP];
#pragma unroll
    for (int k = 0; k < CH; k++)
#pragma unroll
        for (int j = 0; j < NP; j++) acc[k][j] = 0.f;

    const float4* srtb = (const float4*)(g_srt + ((size_t)b * RP) * Lz);
#pragma unroll
    for (int i = 0; i < 16; i++) {
        int idx = ln + i * 32;
        float4 sr[CH];
#pragma unroll
        for (int k = 0; k < CH; k++)
            sr[k] = srtb[(size_t)(rbase + k) * 512 + idx];
#pragma unroll
        for (int j = 0; j < NP; j++) {
            float4 xv = sa4[j * 512 + idx];
#pragma unroll
            for (int k = 0; k < CH; k++) {
                acc[k][j] += sr[k].x * xv.x + sr[k].y * xv.y +
                             sr[k].z * xv.z + sr[k].w * xv.w;
            }
        }
    }

#pragma unroll
    for (int k = 0; k < CH; k++)
#pragma unroll
        for (int j = 0; j < NP; j++) {
#pragma unroll
            for (int off = 16; off > 0; off >>= 1)
                acc[k][j] += __shfl_down_sync(0xffffffffu, acc[k][j], off);
        }

    if (ln == 0) {
#pragma unroll
        for (int k = 0; k < CH; k++) {
            int r = rbase + k;
#pragma unroll
            for (int j = 0; j < NP; j++) {
                sc[(r - r0) * NP + j] = acc[k][j]
                    + g_es[(b * Ez + sarr[j]) * RP + r]
                    + g_eo[(b * Ez + oarr[j]) * RP + r];
            }
        }
    }
    __syncthreads();

    // relation-score writes (rows r0..r0+19 with r < Rz)
    for (int idx = tid; idx < NP * RQ; idx += 128) {
        int j = idx / RQ;
        int lr = idx % RQ;
        int r = r0 + lr;
        if (r < Rz)
            out[((size_t)(b * Pz + pt + j)) * ROUT + 1 + r] = sc[lr * NP + j];
    }
    // NOTA rows occupy exactly quarter 3 (padded rows 60..79)
    if (quarter == 3 && tid < NP) {
        float m = sc[0 * NP + tid];
#pragma unroll
        for (int lr = 1; lr < RQ; lr++) m = fmaxf(m, sc[lr * NP + tid]);
        out[((size_t)(b * Pz + pt + tid)) * ROUT] = m;
    }
}

// ================= launch (graph fork/join; streams/events created ONCE) =========
extern "C" void kernel_launch(void* const* d_in, const int* in_sizes, int n_in,
                              void* d_out, int out_size) {
    const float* seq   = (const float*)d_in[0];   // [B, L, D]
    const float* att   = (const float*)d_in[1];   // [B, H, L, L]
    const float* rel   = (const float*)d_in[2];   // [R, 3D]
    const float* nota  = (const float*)d_in[3];   // [N, 3D]
    const int*   spans = (const int*)d_in[4];     // [B, E]
    float* out = (float*)d_out;                   // [B, P, R+1]

    static cudaStream_t s1 = nullptr, s2 = nullptr;
    static cudaEvent_t evRoot = nullptr, evSrt = nullptr, evEnt = nullptr, evEso = nullptr;
    if (s1 == nullptr) {
        cudaStreamCreateWithFlags(&s1, cudaStreamNonBlocking);
        cudaStreamCreateWithFlags(&s2, cudaStreamNonBlocking);
        cudaEventCreateWithFlags(&evRoot, cudaEventDisableTiming);
        cudaEventCreateWithFlags(&evSrt,  cudaEventDisableTiming);
        cudaEventCreateWithFlags(&evEnt,  cudaEventDisableTiming);
        cudaEventCreateWithFlags(&evEso,  cudaEventDisableTiming);
        cudaFuncSetAttribute(srt_kernel,
                             cudaFuncAttributeMaxDynamicSharedMemorySize, SRT_SMEM);
        int sm = (NP * Lz + RQ * NP + NP) * sizeof(float);
        cudaFuncSetAttribute(ascore_kernel,
                             cudaFuncAttributeMaxDynamicSharedMemorySize, sm);
    }
    int ascore_smem = (NP * Lz + RQ * NP + NP) * sizeof(float);   // ~33.1 KB

    // fork: srt depends only on inputs -> s1
    cudaEventRecord(evRoot, 0);
    cudaStreamWaitEvent(s1, evRoot, 0);
    srt_kernel<<<160, 256, SRT_SMEM, s1>>>(seq, rel, nota);
    cudaEventRecord(evSrt, s1);

    ent_kernel<<<Bz * Ez * Hz, 256>>>(seq, att, spans);
    cudaEventRecord(evEnt, 0);

    // fork: eso depends only on ent -> s2
    cudaStreamWaitEvent(s2, evEnt, 0);
    eso_kernel<<<Bz * RN * 2, 256, 0, s2>>>(rel, nota);
    cudaEventRecord(evEso, s2);

    pair_q_kernel<<<Bz * 256, 128>>>();

    // join: ascore needs pair_q (stream order) + srt + eso
    cudaStreamWaitEvent(0, evSrt, 0);
    cudaStreamWaitEvent(0, evEso, 0);
    ascore_kernel<<<Bz * (Pz / NP) * 4, 128, ascore_smem>>>(out);
}

// round 16
// speedup vs baseline: 1.0462x; 1.0462x over previous
#include <cuda_runtime.h>
#include <cstdint>

#define Bz 2
#define Lz 2048
#define Dz 768
#define Hz 12
#define Ez 32
#define Tz 8
#define Wz 4
#define Rz 57
#define Nz 20
#define Pz 248            // T*(E-1)
#define ROUT (Rz + 1)     // 58
#define RN 77             // R + N rows
#define RP 80             // padded rows: 0..56 rel, 57..59 pad(zero), 60..79 nota
#define NB 248            // persistent grid size (2 blocks/SM on >=124 SMs)

// -------- device scratch --------
__device__ float g_ent_emb[Bz * Ez * Dz];
__device__ float g_ent_att[(size_t)Bz * Ez * Hz * Lz];   // 6.3 MB
__device__ float g_a[(size_t)Bz * Pz * Lz];              // 4 MB (unnormalized q)
__device__ float g_zp[Bz * Pz * 2];                      // per-chunk Z partials
__device__ float g_es[Bz * Ez * RP];                     // pad rows stay 0
__device__ float g_eo[Bz * Ez * RP];
__device__ float g_srt[(size_t)Bz * RP * Lz];            // pad rows = 0
__device__ unsigned g_bar[2];                            // ticket barriers (monotonic)

__device__ __forceinline__ uint32_t f2tf(float f) {
    uint32_t u;
    asm("cvt.rna.tf32.f32 %0, %1;" : "=r"(u) : "f"(f));
    return u;
}

// Monotonic ticket grid barrier: safe across graph replays (no reset needed).
__device__ __forceinline__ void grid_sync(int which) {
    __threadfence();
    __syncthreads();
    if (threadIdx.x == 0) {
        unsigned ticket = atomicAdd(&g_bar[which], 1u);
        unsigned target = (ticket / NB + 1u) * NB;
        while (atomicAdd(&g_bar[which], 0u) < target) { __nanosleep(64); }
    }
    __syncthreads();
}

// ---------------- srt unit (tf32 MMA): 160 units, 256 thr ----------------
#define AS_STRIDE 772
#define BS_STRIDE 36
#define SRT_SMEM ((16 * AS_STRIDE + 128 * BS_STRIDE) * 4)   // 67840 B
__device__ void srt_unit(int u, const float* __restrict__ seq,
                         const float* __restrict__ rel,
                         const float* __restrict__ nota, float* smbuf) {
    float* As = smbuf;
    float* Bs = smbuf + 16 * AS_STRIDE;

    int b = u / 80;
    int rem = u % 80;
    int mt = rem / 16;
    int nt = rem % 16;
    int r0 = mt * 16;
    int l0 = nt * 128;
    int tid = threadIdx.x;
    int w = tid >> 5, lane = tid & 31;

#pragma unroll
    for (int i = 0; i < 12; i++) {
        int f4i = tid + i * 256;
        int rowl = f4i / 192;
        int c4 = f4i % 192;
        int r = r0 + rowl;
        float4 v = make_float4(0.f, 0.f, 0.f, 0.f);
        if (r < Rz)
            v = *(const float4*)(rel + (size_t)r * 3 * Dz + 2 * Dz + c4 * 4);
        else if (r >= 60)
            v = *(const float4*)(nota + (size_t)(r - 60) * 3 * Dz + 2 * Dz + c4 * 4);
        *(float4*)(As + rowl * AS_STRIDE + c4 * 4) = v;
    }

    float acc[2][4];
#pragma unroll
    for (int t = 0; t < 2; t++)
#pragma unroll
        for (int i = 0; i < 4; i++) acc[t][i] = 0.f;

    const float* sbase = seq + (size_t)b * Lz * Dz;
    int arow = lane >> 2, kc = lane & 3;

    for (int d0 = 0; d0 < Dz; d0 += 32) {
        __syncthreads();
#pragma unroll
        for (int i = 0; i < 4; i++) {
            int f4i = tid + i * 256;
            int ll = f4i >> 3;
            int kq = f4i & 7;
            float4 v = *(const float4*)(sbase + (size_t)(l0 + ll) * Dz + d0 + kq * 4);
            *(float4*)(Bs + ll * BS_STRIDE + kq * 4) = v;
        }
        __syncthreads();

#pragma unroll
        for (int k8 = 0; k8 < 4; k8++) {
            int dc = d0 + k8 * 8;
            uint32_t A0 = f2tf(As[arow * AS_STRIDE + dc + kc]);
            uint32_t A1 = f2tf(As[(arow + 8) * AS_STRIDE + dc + kc]);
            uint32_t A2 = f2tf(As[arow * AS_STRIDE + dc + kc + 4]);
            uint32_t A3 = f2tf(As[(arow + 8) * AS_STRIDE + dc + kc + 4]);
#pragma unroll
            for (int t = 0; t < 2; t++) {
                int nl = w * 16 + t * 8 + (lane >> 2);
                uint32_t B0 = f2tf(Bs[nl * BS_STRIDE + k8 * 8 + kc]);
                uint32_t B1 = f2tf(Bs[nl * BS_STRIDE + k8 * 8 + kc + 4]);
                asm volatile(
                    "mma.sync.aligned.m16n8k8.row.col.f32.tf32.tf32.f32 "
                    "{%0,%1,%2,%3}, {%4,%5,%6,%7}, {%8,%9}, {%0,%1,%2,%3};"
                    : "+f"(acc[t][0]), "+f"(acc[t][1]), "+f"(acc[t][2]), "+f"(acc[t][3])
                    : "r"(A0), "r"(A1), "r"(A2), "r"(A3), "r"(B0), "r"(B1));
            }
        }
    }

    int c2 = (lane & 3) * 2;
#pragma unroll
    for (int t = 0; t < 2; t++) {
        int col = l0 + w * 16 + t * 8 + c2;
        float* o0 = g_srt + ((size_t)(b * RP + r0 + arow)) * Lz + col;
        float* o1 = g_srt + ((size_t)(b * RP + r0 + arow + 8)) * Lz + col;
        *(float2*)o0 = make_float2(acc[t][0], acc[t][1]);
        *(float2*)o1 = make_float2(acc[t][2], acc[t][3]);
    }
}

// ---------------- ent unit: 768 units, 256 thr ----------------
__device__ void ent_unit(int y, const float* __restrict__ seq,
                         const float* __restrict__ att,
                         const int* __restrict__ spans) {
    int h = y % Hz;
    int e = (y / Hz) % Ez;
    int b = y / (Ez * Hz);
    int start = spans[b * Ez + e];

    const float4* ab = (const float4*)(att + (((size_t)(b * Hz + h)) * Lz + start) * Lz);
    float4* dst = (float4*)(g_ent_att + ((size_t)((b * Ez + e) * Hz + h)) * Lz);
    for (int i = threadIdx.x; i < Lz / 4; i += 256) {
        float4 v0 = ab[i], v1 = ab[512 + i], v2 = ab[1024 + i], v3 = ab[1536 + i];
        float4 r;
        r.x = (v0.x + v1.x + v2.x + v3.x) * 0.25f;
        r.y = (v0.y + v1.y + v2.y + v3.y) * 0.25f;
        r.z = (v0.z + v1.z + v2.z + v3.z) * 0.25f;
        r.w = (v0.w + v1.w + v2.w + v3.w) * 0.25f;
        dst[i] = r;
    }

    if (h == 0) {
        const float4* sb = (const float4*)(seq + ((size_t)b * Lz + start) * Dz);
        float4* ed = (float4*)(g_ent_emb + (b * Ez + e) * Dz);
        for (int i = threadIdx.x; i < Dz / 4; i += 256) {
            float4 v0 = sb[i], v1 = sb[192 + i], v2 = sb[384 + i], v3 = sb[576 + i];
            float4 r;
            r.x = (v0.x + v1.x + v2.x + v3.x) * 0.25f;
            r.y = (v0.y + v1.y + v2.y + v3.y) * 0.25f;
            r.z = (v0.z + v1.z + v2.z + v3.z) * 0.25f;
            r.w = (v0.w + v1.w + v2.w + v3.w) * 0.25f;
            ed[i] = r;
        }
    }
}

// ---------------- pair_q unit: 128 units (2o x 4s x L-split 2), 256 thr ----------
__device__ void pairq_unit(int u, float* smbuf) {
    int b = u >> 6;
    int rem = u & 63;
    int c = rem & 1;              // L chunk (1024 floats)
    int sh = (rem >> 1) & 1;
    int og = rem >> 2;            // 0..15
    int o0 = og * 2;
    int s0 = sh * 4;
    int tid = threadIdx.x;
    int f4idx = c * 256 + tid;    // 0..511

    const float4* aob[2];
    const float4* asb[4];
#pragma unroll
    for (int oo = 0; oo < 2; oo++)
        aob[oo] = (const float4*)(g_ent_att + ((size_t)((b * Ez + o0 + oo) * Hz)) * Lz);
#pragma unroll
    for (int js = 0; js < 4; js++)
        asb[js] = (const float4*)(g_ent_att + ((size_t)((b * Ez + s0 + js) * Hz)) * Lz);

    float4 q[2][4];
#pragma unroll
    for (int oo = 0; oo < 2; oo++)
#pragma unroll
        for (int js = 0; js < 4; js++)
            q[oo][js] = make_float4(0.f, 0.f, 0.f, 0.f);

#pragma unroll
    for (int h = 0; h < Hz; h++) {
        float4 ao0 = aob[0][h * 512 + f4idx];
        float4 ao1 = aob[1][h * 512 + f4idx];
#pragma unroll
        for (int js = 0; js < 4; js++) {
            float4 as = asb[js][h * 512 + f4idx];
            q[0][js].x += as.x * ao0.x; q[0][js].y += as.y * ao0.y;
            q[0][js].z += as.z * ao0.z; q[0][js].w += as.w * ao0.w;
            q[1][js].x += as.x * ao1.x; q[1][js].y += as.y * ao1.y;
            q[1][js].z += as.z * ao1.z; q[1][js].w += as.w * ao1.w;
        }
    }

    float* red = smbuf;           // 256 x 8 floats = 8 KB
#pragma unroll
    for (int oo = 0; oo < 2; oo++)
#pragma unroll
        for (int js = 0; js < 4; js++) {
            float4 t = q[oo][js];
            red[tid * 8 + oo * 4 + js] = t.x + t.y + t.z + t.w;
        }
    __syncthreads();
#pragma unroll
    for (int st = 128; st > 0; st >>= 1) {
        if (tid < st) {
#pragma unroll
            for (int k = 0; k < 8; k++) red[tid * 8 + k] += red[(tid + st) * 8 + k];
        }
        __syncthreads();
    }

#pragma unroll
    for (int oo = 0; oo < 2; oo++) {
        int o = o0 + oo;
#pragma unroll
        for (int js = 0; js < 4; js++) {
            int s = s0 + js;
            if (s == o) continue;
            int jj = o - (o > s ? 1 : 0);
            int p = s * (Ez - 1) + jj;
            ((float4*)(g_a + ((size_t)(b * Pz + p)) * Lz))[f4idx] = q[oo][js];
            if (tid == 0)
                g_zp[(b * Pz + p) * 2 + c] = red[oo * 4 + js];
        }
    }
}

// ---------------- eso unit: 308 units, 256 thr ----------------
__device__ void eso_unit(int x, const float* __restrict__ rel,
                         const float* __restrict__ nota, float* smbuf) {
    int b = x / (RN * 2);
    int rr = x % (RN * 2);
    int ri = rr >> 1;
    int half = rr & 1;
    int rlog = (ri < Rz) ? ri : ri + 3;
    int tid = threadIdx.x;

    float4* w = (float4*)smbuf;   // 384 float4 = 6 KB
    const float4* row = (const float4*)((ri < Rz) ? (rel + (size_t)ri * 3 * Dz)
                                                  : (nota + (size_t)(ri - Rz) * 3 * Dz));
    for (int i = tid; i < 2 * Dz / 4; i += 256) w[i] = row[i];
    __syncthreads();

    int wp = tid >> 5, ln = tid & 31;
#pragma unroll
    for (int ee = 0; ee < 2; ee++) {
        int e = half * 16 + wp + ee * 8;
        const float4* emb = (const float4*)(g_ent_emb + (b * Ez + e) * Dz);
        float es = 0.f, eo = 0.f;
#pragma unroll
        for (int i = 0; i < 6; i++) {
            int d = ln + i * 32;
            float4 e4 = emb[d];
            float4 r1 = w[d];
            float4 r2 = w[Dz / 4 + d];
            es += e4.x * r1.x + e4.y * r1.y + e4.z * r1.z + e4.w * r1.w;
            eo += e4.x * r2.x + e4.y * r2.y + e4.z * r2.z + e4.w * r2.w;
        }
#pragma unroll
        for (int off = 16; off > 0; off >>= 1) {
            es += __shfl_down_sync(0xffffffffu, es, off);
            eo += __shfl_down_sync(0xffffffffu, eo, off);
        }
        if (ln == 0) {
            g_es[(b * Ez + e) * RP + rlog] = es;
            g_eo[(b * Ez + e) * RP + rlog] = eo;
        }
    }
}

// ---------------- ascore unit: 248 units (NP=4, row-half 40, 8 warps x 5), 256 thr
#define NP 4
#define RH 40
#define CH 5
__device__ void ascore_unit(int u, float* __restrict__ out, float* smbuf) {
    float* sa = smbuf;                    // NP * Lz = 32 KB
    float* sc = smbuf + NP * Lz;          // RH * NP
    float* sInv = sc + RH * NP;           // NP

    int b = u / 124;
    int rem = u % 124;
    int pt = (rem >> 1) * NP;
    int half = rem & 1;
    int r0 = half * RH;
    int tid = threadIdx.x;

    int sarr[NP], oarr[NP];
#pragma unroll
    for (int j = 0; j < NP; j++) {
        int p = pt + j;
        int s = p / (Ez - 1);
        int jj = p % (Ez - 1);
        sarr[j] = s;
        oarr[j] = jj + (jj >= s ? 1 : 0);
    }

    if (tid < NP) {
        int p = b * Pz + pt + tid;
        sInv[tid] = 1.0f / (g_zp[p * 2] + g_zp[p * 2 + 1]);
    }
    __syncthreads();

    float4* sa4 = (float4*)sa;
    for (int idx = tid; idx < NP * (Lz / 4); idx += 256) {
        int j = idx >> 9;
        int c = idx & 511;
        float inv = sInv[j];
        float4 v = ((const float4*)(g_a + ((size_t)(b * Pz + pt + j)) * Lz))[c];
        sa4[j * 512 + c] = make_float4(v.x * inv, v.y * inv, v.z * inv, v.w * inv);
    }
    __syncthreads();

    int w = tid >> 5, ln = tid & 31;
    int rbase = r0 + w * CH;

    float acc[CH][NP];
#pragma unroll
    for (int k = 0; k < CH; k++)
#pragma unroll
        for (int j = 0; j < NP; j++) acc[k][j] = 0.f;

    const float4* srtb = (const float4*)(g_srt + ((size_t)b * RP) * Lz);
#pragma unroll
    for (int i = 0; i < 16; i++) {
        int idx = ln + i * 32;
        float4 sr[CH];
#pragma unroll
        for (int k = 0; k < CH; k++)
            sr[k] = srtb[(size_t)(rbase + k) * 512 + idx];
#pragma unroll
        for (int j = 0; j < NP; j++) {
            float4 xv = sa4[j * 512 + idx];
#pragma unroll
            for (int k = 0; k < CH; k++) {
                acc[k][j] += sr[k].x * xv.x + sr[k].y * xv.y +
                             sr[k].z * xv.z + sr[k].w * xv.w;
            }
        }
    }

#pragma unroll
    for (int k = 0; k < CH; k++)
#pragma unroll
        for (int j = 0; j < NP; j++) {
#pragma unroll
            for (int off = 16; off > 0; off >>= 1)
                acc[k][j] += __shfl_down_sync(0xffffffffu, acc[k][j], off);
        }

    if (ln == 0) {
#pragma unroll
        for (int k = 0; k < CH; k++) {
            int r = rbase + k;
#pragma unroll
            for (int j = 0; j < NP; j++) {
                sc[(r - r0) * NP + j] = acc[k][j]
                    + g_es[(b * Ez + sarr[j]) * RP + r]
                    + g_eo[(b * Ez + oarr[j]) * RP + r];
            }
        }
    }
    __syncthreads();

    for (int idx = tid; idx < NP * RH; idx += 256) {
        int j = idx / RH;
        int lr = idx % RH;
        int r = r0 + lr;
        if (r < Rz)
            out[((size_t)(b * Pz + pt + j)) * ROUT + 1 + r] = sc[lr * NP + j];
    }
    // NOTA rows 60..79 live in half 1 (local rows 20..39)
    if (half == 1 && tid < NP) {
        float m = sc[20 * NP + tid];
#pragma unroll
        for (int lr = 21; lr < RH; lr++) m = fmaxf(m, sc[lr * NP + tid]);
        out[((size_t)(b * Pz + pt + tid)) * ROUT] = m;
    }
}

// ================= persistent mega-kernel =================
#define P1_UNITS (160 + Bz * Ez * Hz)        // 928
#define P2_UNITS (128 + Bz * RN * 2)         // 436
#define P3_UNITS 248
__global__ void __launch_bounds__(256, 2)
mega_kernel(const float* __restrict__ seq, const float* __restrict__ att,
            const float* __restrict__ rel, const float* __restrict__ nota,
            const int* __restrict__ spans, float* __restrict__ out) {
    extern __shared__ float smbuf[];

    // Phase 1: srt (tile GEMM) + ent (span means)
    for (int u = blockIdx.x; u < P1_UNITS; u += NB) {
        if (u < 160) srt_unit(u, seq, rel, nota, smbuf);
        else         ent_unit(u - 160, seq, att, spans);
        __syncthreads();
    }
    grid_sync(0);

    // Phase 2: pair_q + eso
    for (int u = blockIdx.x; u < P2_UNITS; u += NB) {
        if (u < 128) pairq_unit(u, smbuf);
        else         eso_unit(u - 128, rel, nota, smbuf);
        __syncthreads();
    }
    grid_sync(1);

    // Phase 3: ascore
    for (int u = blockIdx.x; u < P3_UNITS; u += NB) {
        ascore_unit(u, out, smbuf);
        __syncthreads();
    }
}

// ================= launch =================
extern "C" void kernel_launch(void* const* d_in, const int* in_sizes, int n_in,
                              void* d_out, int out_size) {
    const float* seq   = (const float*)d_in[0];   // [B, L, D]
    const float* att   = (const float*)d_in[1];   // [B, H, L, L]
    const float* rel   = (const float*)d_in[2];   // [R, 3D]
    const float* nota  = (const float*)d_in[3];   // [N, 3D]
    const int*   spans = (const int*)d_in[4];     // [B, E]
    float* out = (float*)d_out;                   // [B, P, R+1]

    static bool init = false;
    if (!init) {
        cudaFuncSetAttribute(mega_kernel,
                             cudaFuncAttributeMaxDynamicSharedMemorySize, SRT_SMEM);
        init = true;
    }
    mega_kernel<<<NB, 256, SRT_SMEM>>>(seq, att, rel, nota, spans, out);
}